// round 14
// baseline (speedup 1.0000x reference)
#include <cuda_runtime.h>
#include <cuda_fp16.h>
#include <stdint.h>

// MessagePassing: out[dst[e]] += x[src[e]], N=100000, E=1600000, D=32 fp32.
// edge_index int32 [2, E]: row 0 = src, row 1 = dst.
//
// fp32 edge-centric scatter is converged at the LTS sector ceiling
// (423MB @ ~11.2TB/s = 38us). This version cuts gather traffic 2x by
// pre-converting x to fp16 (messages only; accumulation stays fp32 via
// RED.128): per-edge sectors 264B -> 200B => ~320MB => ~29us scatter.
// Precision: fp16 message round-off => norm rel_err ~3e-4 << 1e-3.

#define D_FEAT   32
#define CHUNKS   8          // float4 chunks per row
#define HCHUNKS  8          // uint2 (4-half) chunks per fp16 row
#define EPT      8          // edges per thread-group
#define MAX_NODES 131072

// fp16 copy of x: MAX_NODES rows x 32 halves = 8 uint2 per row (8.4 MB).
__device__ uint2 g_xh[(long)MAX_NODES * HCHUNKS];

__device__ __forceinline__ void red_add_v4(float* p, float4 v) {
    asm volatile("red.global.add.v4.f32 [%0], {%1, %2, %3, %4};"
                 :: "l"(p), "f"(v.x), "f"(v.y), "f"(v.z), "f"(v.w)
                 : "memory");
}

// Convert x (float4 chunks) -> g_xh (uint2 = 4 halves), 1:1 chunk mapping.
__global__ void mp_cvt_kernel(const float4* __restrict__ x, long n4) {
    long i = (long)blockIdx.x * blockDim.x + threadIdx.x;
    if (i >= n4) return;
    float4 v = __ldg(&x[i]);
    __half2 h0 = __floats2half2_rn(v.x, v.y);
    __half2 h1 = __floats2half2_rn(v.z, v.w);
    uint2 u;
    u.x = *reinterpret_cast<unsigned*>(&h0);
    u.y = *reinterpret_cast<unsigned*>(&h1);
    g_xh[i] = u;
}

__device__ __forceinline__ float4 h4_to_f4(uint2 u) {
    __half2 h0 = *reinterpret_cast<__half2*>(&u.x);
    __half2 h1 = *reinterpret_cast<__half2*>(&u.y);
    float2 f0 = __half22float2(h0);
    float2 f1 = __half22float2(h1);
    return make_float4(f0.x, f0.y, f1.x, f1.y);
}

// Scatter: 8 lanes per edge-group (lane c owns 16B of the fp32 output row,
// i.e. 8B of the fp16 source row); 8 edges per group, gathers batched MLP=8.
__global__ void mp_scatter_h_kernel(const int* __restrict__ src,
                                    const int* __restrict__ dst,
                                    float* __restrict__ out,
                                    long n_edges) {
    long t = (long)blockIdx.x * blockDim.x + threadIdx.x;
    long g = t >> 3;
    int  c = (int)(t & 7);
    long e0 = g * EPT;
    if (e0 >= n_edges) return;

    if (e0 + EPT <= n_edges) {
        int4 sa = __ldg((const int4*)(src + e0));
        int4 sb = __ldg((const int4*)(src + e0 + 4));
        int4 da = __ldg((const int4*)(dst + e0));
        int4 db = __ldg((const int4*)(dst + e0 + 4));

        // 8 independent 8B gathers (MLP=8), 2 sectors per row group-wide.
        uint2 u0 = __ldg(&g_xh[(long)sa.x * HCHUNKS + c]);
        uint2 u1 = __ldg(&g_xh[(long)sa.y * HCHUNKS + c]);
        uint2 u2 = __ldg(&g_xh[(long)sa.z * HCHUNKS + c]);
        uint2 u3 = __ldg(&g_xh[(long)sa.w * HCHUNKS + c]);
        uint2 u4 = __ldg(&g_xh[(long)sb.x * HCHUNKS + c]);
        uint2 u5 = __ldg(&g_xh[(long)sb.y * HCHUNKS + c]);
        uint2 u6 = __ldg(&g_xh[(long)sb.z * HCHUNKS + c]);
        uint2 u7 = __ldg(&g_xh[(long)sb.w * HCHUNKS + c]);

        int co = c * 4;
        red_add_v4(out + (long)da.x * D_FEAT + co, h4_to_f4(u0));
        red_add_v4(out + (long)da.y * D_FEAT + co, h4_to_f4(u1));
        red_add_v4(out + (long)da.z * D_FEAT + co, h4_to_f4(u2));
        red_add_v4(out + (long)da.w * D_FEAT + co, h4_to_f4(u3));
        red_add_v4(out + (long)db.x * D_FEAT + co, h4_to_f4(u4));
        red_add_v4(out + (long)db.y * D_FEAT + co, h4_to_f4(u5));
        red_add_v4(out + (long)db.z * D_FEAT + co, h4_to_f4(u6));
        red_add_v4(out + (long)db.w * D_FEAT + co, h4_to_f4(u7));
    } else {
        for (long e = e0; e < n_edges; ++e) {
            int s = __ldg(&src[e]);
            int d = __ldg(&dst[e]);
            uint2 u = __ldg(&g_xh[(long)s * HCHUNKS + c]);
            red_add_v4(out + (long)d * D_FEAT + c * 4, h4_to_f4(u));
        }
    }
}

// fp32 fallback (shape safety): R8 kernel, byte-identical structure.
__global__ void mp_scatter_kernel(const float4* __restrict__ x,
                                  const int* __restrict__ src,
                                  const int* __restrict__ dst,
                                  float* __restrict__ out,
                                  long n_edges) {
    long t = (long)blockIdx.x * blockDim.x + threadIdx.x;
    long g = t >> 3;
    int  c = (int)(t & 7);
    long e0 = g * EPT;
    if (e0 >= n_edges) return;

    if (e0 + EPT <= n_edges) {
        int4 sa = __ldg((const int4*)(src + e0));
        int4 sb = __ldg((const int4*)(src + e0 + 4));
        int4 da = __ldg((const int4*)(dst + e0));
        int4 db = __ldg((const int4*)(dst + e0 + 4));
        float4 v0 = __ldg(&x[(long)sa.x * CHUNKS + c]);
        float4 v1 = __ldg(&x[(long)sa.y * CHUNKS + c]);
        float4 v2 = __ldg(&x[(long)sa.z * CHUNKS + c]);
        float4 v3 = __ldg(&x[(long)sa.w * CHUNKS + c]);
        float4 v4 = __ldg(&x[(long)sb.x * CHUNKS + c]);
        float4 v5 = __ldg(&x[(long)sb.y * CHUNKS + c]);
        float4 v6 = __ldg(&x[(long)sb.z * CHUNKS + c]);
        float4 v7 = __ldg(&x[(long)sb.w * CHUNKS + c]);
        int co = c * 4;
        red_add_v4(out + (long)da.x * D_FEAT + co, v0);
        red_add_v4(out + (long)da.y * D_FEAT + co, v1);
        red_add_v4(out + (long)da.z * D_FEAT + co, v2);
        red_add_v4(out + (long)da.w * D_FEAT + co, v3);
        red_add_v4(out + (long)db.x * D_FEAT + co, v4);
        red_add_v4(out + (long)db.y * D_FEAT + co, v5);
        red_add_v4(out + (long)db.z * D_FEAT + co, v6);
        red_add_v4(out + (long)db.w * D_FEAT + co, v7);
    } else {
        for (long e = e0; e < n_edges; ++e) {
            int s = __ldg(&src[e]);
            int d = __ldg(&dst[e]);
            float4 v = __ldg(&x[(long)s * CHUNKS + c]);
            red_add_v4(out + (long)d * D_FEAT + c * 4, v);
        }
    }
}

extern "C" void kernel_launch(void* const* d_in, const int* in_sizes, int n_in,
                              void* d_out, int out_size) {
    const float4* x   = (const float4*)d_in[0];
    const int*    ei  = (const int*)d_in[1];
    long n_edges = (long)in_sizes[1] / 2;
    const int* src = ei;
    const int* dst = ei + n_edges;
    float* out = (float*)d_out;
    int n_nodes = in_sizes[0] / D_FEAT;
    int threads = 256;

    // Zero the (poisoned) output via a memset node.
    cudaMemsetAsync(d_out, 0, (size_t)out_size * sizeof(float), 0);

    long groups = (n_edges + EPT - 1) / EPT;
    long total  = groups * 8;
    long blocks = (total + threads - 1) / threads;

    if (n_nodes > MAX_NODES) {
        // Shape safety: fp32 path.
        mp_scatter_kernel<<<(unsigned)blocks, threads>>>(x, src, dst, out, n_edges);
        return;
    }

    // Convert x -> fp16 scratch.
    long n4 = (long)in_sizes[0] / 4;
    long cblocks = (n4 + threads - 1) / threads;
    mp_cvt_kernel<<<(unsigned)cblocks, threads>>>(x, n4);

    // fp16-gather scatter.
    mp_scatter_h_kernel<<<(unsigned)blocks, threads>>>(src, dst, out, n_edges);
}

// round 16
// speedup vs baseline: 1.0527x; 1.0527x over previous
#include <cuda_runtime.h>
#include <stdint.h>

// MessagePassing: out[dst[e]] += x[src[e]], N=100000, E=1600000, D=32 fp32.
// edge_index stored as int32 [2, E] (JAX x64-disabled). Row 0 = src, row 1 = dst.
//
// CONVERGED KERNEL (best measured: 41.47us total, scatter 37.7us).
// 8 lanes per group cover one 128B feature row (float4/lane). Each group
// processes EPT=8 edges: indices loaded as int4 (2 LDG.128 per array),
// all 8 gathers issued before any RED (MLP=8), scatter via
// red.global.add.v4.f32 (fire-and-forget RED.128, max vector width on
// sm_103a). Per-edge cost: 1 gather wavefront + 1 RED wavefront -- the
// structural minimum; measured ~3 cyc/wf vs ~2 cyc/wf L1TEX floor.
// Evidence of convergence: fp16 gathers (half the bytes) moved scatter only
// -2% (wavefront-bound, not byte-bound); EPT=16 regressed (occupancy);
// 6 sort/bin restructures all lost to reorder cost; v8.f32 RED rejected.

#define D_FEAT 32
#define CHUNKS 8   // D_FEAT / 4
#define EPT    8   // edges per thread-group

__global__ void mp_zero_kernel(float4* __restrict__ out, long n4) {
    long i = (long)blockIdx.x * blockDim.x + threadIdx.x;
    if (i < n4) out[i] = make_float4(0.f, 0.f, 0.f, 0.f);
}

__device__ __forceinline__ void red_add_v4(float* p, float4 v) {
    asm volatile("red.global.add.v4.f32 [%0], {%1, %2, %3, %4};"
                 :: "l"(p), "f"(v.x), "f"(v.y), "f"(v.z), "f"(v.w)
                 : "memory");
}

__global__ void mp_scatter_kernel(const float4* __restrict__ x,
                                  const int* __restrict__ src,
                                  const int* __restrict__ dst,
                                  float* __restrict__ out,
                                  long n_edges) {
    long t = (long)blockIdx.x * blockDim.x + threadIdx.x;
    long g = t >> 3;          // edge-group index
    int  c = (int)(t & 7);    // 16B chunk within the 128B feature row
    long e0 = g * EPT;
    if (e0 >= n_edges) return;

    if (e0 + EPT <= n_edges) {
        // Vectorized index loads: e0 is a multiple of 8 -> 16B aligned.
        int4 sa = __ldg((const int4*)(src + e0));
        int4 sb = __ldg((const int4*)(src + e0 + 4));
        int4 da = __ldg((const int4*)(dst + e0));
        int4 db = __ldg((const int4*)(dst + e0 + 4));

        // Batch all 8 gathers (MLP=8) before any RED.
        float4 v0 = __ldg(&x[(long)sa.x * CHUNKS + c]);
        float4 v1 = __ldg(&x[(long)sa.y * CHUNKS + c]);
        float4 v2 = __ldg(&x[(long)sa.z * CHUNKS + c]);
        float4 v3 = __ldg(&x[(long)sa.w * CHUNKS + c]);
        float4 v4 = __ldg(&x[(long)sb.x * CHUNKS + c]);
        float4 v5 = __ldg(&x[(long)sb.y * CHUNKS + c]);
        float4 v6 = __ldg(&x[(long)sb.z * CHUNKS + c]);
        float4 v7 = __ldg(&x[(long)sb.w * CHUNKS + c]);

        int co = c * 4;
        red_add_v4(out + (long)da.x * D_FEAT + co, v0);
        red_add_v4(out + (long)da.y * D_FEAT + co, v1);
        red_add_v4(out + (long)da.z * D_FEAT + co, v2);
        red_add_v4(out + (long)da.w * D_FEAT + co, v3);
        red_add_v4(out + (long)db.x * D_FEAT + co, v4);
        red_add_v4(out + (long)db.y * D_FEAT + co, v5);
        red_add_v4(out + (long)db.z * D_FEAT + co, v6);
        red_add_v4(out + (long)db.w * D_FEAT + co, v7);
    } else {
        // Tail: scalar loop over remaining edges (not taken for E=1.6M).
        for (long e = e0; e < n_edges; ++e) {
            int s = __ldg(&src[e]);
            int d = __ldg(&dst[e]);
            float4 v = __ldg(&x[(long)s * CHUNKS + c]);
            red_add_v4(out + (long)d * D_FEAT + c * 4, v);
        }
    }
}

extern "C" void kernel_launch(void* const* d_in, const int* in_sizes, int n_in,
                              void* d_out, int out_size) {
    const float4* x   = (const float4*)d_in[0];
    const int*    ei  = (const int*)d_in[1];
    long n_edges = (long)in_sizes[1] / 2;      // edge_index has 2*E elements
    const int* src = ei;                       // row 0
    const int* dst = ei + n_edges;             // row 1
    float* out = (float*)d_out;

    // Zero the (poisoned) output.
    long n4 = (long)out_size / 4;
    {
        int threads = 256;
        long blocks = (n4 + threads - 1) / threads;
        mp_zero_kernel<<<(unsigned)blocks, threads>>>((float4*)out, n4);
    }

    // Scatter-add: 8 lanes per edge-group, 8 edges per group.
    {
        long total = ((n_edges + EPT - 1) / EPT) * 8;
        int threads = 256;
        long blocks = (total + threads - 1) / threads;
        mp_scatter_kernel<<<(unsigned)blocks, threads>>>(x, src, dst, out, n_edges);
    }
}